// round 15
// baseline (speedup 1.0000x reference)
#include <cuda_runtime.h>
#include <cstdint>

// Problem constants (fixed by setup_inputs): B=8, N=20, K=5, Q=15, D=1024
#define BB     8
#define NN     20
#define KSUP   5
#define QQ     15
#define DD     1024
#define ROWS   (KSUP + QQ)        // 20 rows per (b,n)
#define NQ     (NN * QQ)          // 300 queries per batch
#define WARPS  16
#define THREADS 512
#define BPB    19                 // blocks per batch (19*16=304 >= 300 queries)
#define GRID   (BB * BPB)         // 152 blocks == GB300 SM count, single wave

#define TILE_BYTES (NN * DD * 4)  // 81920

// Scratch (device globals — no allocation allowed)
__device__ float g_proto[BB * NN * DD];   // 640 KB, L2-resident

// ---- minimal mbarrier / bulk-copy PTX ----
__device__ __forceinline__ uint32_t smem_u32(const void* p) {
    return (uint32_t)__cvta_generic_to_shared(p);
}
#define MBAR_INIT(a, cnt) \
    asm volatile("mbarrier.init.shared.b64 [%0], %1;" :: "r"(a), "r"(cnt) : "memory")
#define MBAR_EXPECT_TX(a, bytes) \
    asm volatile("mbarrier.arrive.expect_tx.shared.b64 _, [%0], %1;" :: "r"(a), "r"(bytes) : "memory")
#define BULK_G2S(dst, src, bytes, mbar) \
    asm volatile("cp.async.bulk.shared::cluster.global.mbarrier::complete_tx::bytes [%0], [%1], %2, [%3];" \
                 :: "r"(dst), "l"(src), "r"(bytes), "r"(mbar) : "memory")
#define MBAR_WAIT(a, par) do {                                            \
    asm volatile(                                                         \
        "{\n\t.reg .pred P1;\n\t"                                         \
        "WAIT_%=:\n\t"                                                    \
        "mbarrier.try_wait.parity.acquire.cta.shared::cta.b64 P1, [%0], %1, 0x989680;\n\t" \
        "@P1 bra.uni DONE_%=;\n\t"                                        \
        "bra.uni WAIT_%=;\n\t"                                            \
        "DONE_%=:\n\t}"                                                   \
        :: "r"(a), "r"(par) : "memory");                                  \
} while (0)

// ---------------------------------------------------------------------------
// K1 (slim): proto[b,n,:] = mean_j support. No reductions, no smem, no bar.
// Triggers PDL completion so relnet can start its prolog under our tail.
// ---------------------------------------------------------------------------
__global__ __launch_bounds__(128) void proto_kernel(const float* __restrict__ emb)
{
    const int bn   = blockIdx.x >> 1;
    const int half = blockIdx.x & 1;
    const int t    = threadIdx.x;             // f4 index within half
    const float4* base = reinterpret_cast<const float4*>(emb)
                       + (size_t)bn * ROWS * 256 + half * 128 + t;
    float4 s = base[0];
#pragma unroll
    for (int j = 1; j < KSUP; j++) {
        const float4 v = base[j * 256];
        s.x += v.x; s.y += v.y; s.z += v.z; s.w += v.w;
    }
    s.x *= 0.2f; s.y *= 0.2f; s.z *= 0.2f; s.w *= 0.2f;
    reinterpret_cast<float4*>(g_proto)[(size_t)bn * 256 + half * 128 + t] = s;

    cudaTriggerProgrammaticLaunchCompletion();
}

// ---------------------------------------------------------------------------
// Main: 152 blocks (= SM count) x 512 threads, one batch per block, single
// wave. PDL prolog (query/weight LDGs, reg math) overlaps proto's tail; the
// 80KB proto tile arrives via ONE cp.async.bulk (issue-free for the block)
// signaled by an mbarrier. Hot loop = R11 FMA structure + cross-nb prefetch.
// ---------------------------------------------------------------------------
__global__ __launch_bounds__(THREADS, 1) void relnet_kernel(
    const float* __restrict__ emb,
    const float* __restrict__ weight,
    const float* __restrict__ bias,
    float* __restrict__ out)
{
    extern __shared__ float smem[];
    float4* sP4 = reinterpret_cast<float4*>(smem);               // 20*256 f4 = 81920 B
    float4* sW2 = reinterpret_cast<float4*>(smem + NN * DD);     // 256 f4    =  4096 B
    float*  sTp = smem + NN * DD + 1024;                         // 20 floats (+12 pad)
    unsigned long long* mbar =
        reinterpret_cast<unsigned long long*>(smem + NN * DD + 1024 + 32);

    const int tid  = threadIdx.x;
    const int lane = tid & 31;
    const int warp = tid >> 5;

    const int b      = blockIdx.x / BPB;          // batch
    const int blkInB = blockIdx.x - b * BPB;      // 0..18
    const int q      = blkInB * WARPS + warp;     // 0..303
    const bool active = (q < NQ);
    const int qc     = active ? q : (NQ - 1);     // clamped for safe addressing

    const float4* emb4 = reinterpret_cast<const float4*>(emb);
    const float4* w04  = reinterpret_cast<const float4*>(weight);
    const float4* w14  = w04 + 1 * 256;
    const float4* w24  = w04 + 2 * 256;
    const float4* w34  = w04 + 3 * 256;
    const float bi = bias[0];

    const uint32_t mbarA = smem_u32(mbar);

    // ---- PDL prolog: LDGs that do NOT depend on g_proto, issued early ----
    const int qrow = (b * NN + qc / QQ) * ROWS + KSUP + qc % QQ;
    const float4* r = emb4 + (size_t)qrow * 256;

    float4 av[8], w3v[8], w1v[8];
#pragma unroll
    for (int i = 0; i < 8; i++) {
        const int idx = i * 32 + lane;
        av[i]  = r[idx];
        w3v[i] = w34[idx];
        w1v[i] = w14[idx];
    }
    if (tid < 256) sW2[tid] = w24[tid];
    if (tid == 0) MBAR_INIT(mbarA, 1);
    __syncthreads();   // mbar init + sW2 visible

    // one thread: wait for proto (PDL), then kick the 80KB bulk copy
    if (tid == 0) {
        cudaGridDependencySynchronize();
        MBAR_EXPECT_TX(mbarA, TILE_BYTES);
        BULK_G2S(smem_u32(sP4), (const void*)(g_proto + (size_t)b * NN * DD),
                 TILE_BYTES, mbarA);
    }

    // ---- derive qv / cv / tq (register work, overlaps the DMA) ----
    float qv[32], cv[32];
    float tq = 0.f;
#pragma unroll
    for (int i = 0; i < 8; i++) {
        const float4 a  = av[i];
        const float4 w3 = w3v[i];
        const float4 w1 = w1v[i];
        qv[4*i+0] = a.x; qv[4*i+1] = a.y; qv[4*i+2] = a.z; qv[4*i+3] = a.w;
        cv[4*i+0] = a.x * w3.x; cv[4*i+1] = a.y * w3.y;
        cv[4*i+2] = a.z * w3.z; cv[4*i+3] = a.w * w3.w;
        tq = fmaf(a.x, w1.x, tq); tq = fmaf(a.y, w1.y, tq);
        tq = fmaf(a.z, w1.z, tq); tq = fmaf(a.w, w1.w, tq);
    }
#pragma unroll
    for (int off = 16; off; off >>= 1) tq += __shfl_xor_sync(0xFFFFFFFFu, tq, off);

    // ---- wait for the proto tile ----
    MBAR_WAIT(mbarA, 0);

    // ---- term_p in-block: 20 warp dot-products over the smem tile ----
#pragma unroll 1
    for (int n = warp; n < NN; n += WARPS) {
        const float4* pr = sP4 + n * 256;
        float tp = 0.f;
#pragma unroll
        for (int i = 0; i < 8; i++) {
            const int idx = i * 32 + lane;
            const float4 p  = pr[idx];
            const float4 w0 = __ldg(w04 + idx);
            tp = fmaf(p.x, w0.x, tp); tp = fmaf(p.y, w0.y, tp);
            tp = fmaf(p.z, w0.z, tp); tp = fmaf(p.w, w0.w, tp);
        }
#pragma unroll
        for (int off = 16; off; off >>= 1) tp += __shfl_xor_sync(0xFFFFFFFFu, tp, off);
        if (lane == 0) sTp[n] = tp;
    }
    __syncthreads();

    if (!active) return;

    float* o = out + ((size_t)b * NQ + q) * NN;

    // ---- hot loop: 5 n-blocks of 4, prefetch over i AND across nb ----
    const float4* pb = sP4 + lane;            // + nb*1024 + n*256 + i*32

    float4 pc[4], pn[4], w2c, w2n;
    w2c = sW2[lane];
#pragma unroll
    for (int n = 0; n < 4; n++) pc[n] = pb[n * 256];

#pragma unroll 1
    for (int nb = 0; nb < 5; nb++) {
        float acc[4] = {0.f, 0.f, 0.f, 0.f};

#pragma unroll
        for (int i = 0; i < 8; i++) {
            const bool pf = (i < 7) || (nb < 4);
            if (pf) {
                const float4* nbase;
                if (i < 7) {
                    w2n = sW2[(i + 1) * 32 + lane];
                    nbase = pb + nb * 1024 + (i + 1) * 32;
                } else {
                    w2n = sW2[lane];
                    nbase = pb + (nb + 1) * 1024;
                }
#pragma unroll
                for (int n = 0; n < 4; n++) pn[n] = nbase[n * 256];
            }
#pragma unroll
            for (int n = 0; n < 4; n++) {
                const float4 p = pc[n];
                acc[n] = fmaf(fabsf(p.x - qv[4*i+0]), w2c.x, acc[n]);
                acc[n] = fmaf(p.x, cv[4*i+0], acc[n]);
                acc[n] = fmaf(fabsf(p.y - qv[4*i+1]), w2c.y, acc[n]);
                acc[n] = fmaf(p.y, cv[4*i+1], acc[n]);
                acc[n] = fmaf(fabsf(p.z - qv[4*i+2]), w2c.z, acc[n]);
                acc[n] = fmaf(p.z, cv[4*i+2], acc[n]);
                acc[n] = fmaf(fabsf(p.w - qv[4*i+3]), w2c.w, acc[n]);
                acc[n] = fmaf(p.w, cv[4*i+3], acc[n]);
            }
            if (pf) {
#pragma unroll
                for (int n = 0; n < 4; n++) pc[n] = pn[n];
                w2c = w2n;
            }
        }

        // deferred reductions: 4 independent butterflies per n-block
#pragma unroll
        for (int n = 0; n < 4; n++) {
            float s = acc[n];
#pragma unroll
            for (int off = 16; off; off >>= 1)
                s += __shfl_xor_sync(0xFFFFFFFFu, s, off);
            acc[n] = s;
        }
        if (lane == 0) {
#pragma unroll
            for (int n = 0; n < 4; n++) {
                const int nn = nb * 4 + n;
                o[nn] = acc[n] + sTp[nn] + tq + bi;
            }
        }
    }
}

// ---------------------------------------------------------------------------
// Launch: slim proto, then relnet with PDL (programmatic stream
// serialization) so relnet's prolog overlaps proto's tail.
// ---------------------------------------------------------------------------
static const int SMEM_BYTES = (NN * DD + 1024 + 32 + 8) * (int)sizeof(float); // 86,176 B

extern "C" void kernel_launch(void* const* d_in, const int* in_sizes, int n_in,
                              void* d_out, int out_size)
{
    const float* emb    = (const float*)d_in[0];
    const float* weight = (const float*)d_in[1];
    const float* bias   = (const float*)d_in[2];
    float* out          = (float*)d_out;

    cudaFuncSetAttribute(relnet_kernel,
                         cudaFuncAttributeMaxDynamicSharedMemorySize, SMEM_BYTES);

    proto_kernel<<<BB * NN * 2, 128>>>(emb);

    cudaLaunchAttribute attrs[1];
    attrs[0].id = cudaLaunchAttributeProgrammaticStreamSerialization;
    attrs[0].val.programmaticStreamSerializationAllowed = 1;

    cudaLaunchConfig_t cfg = {};
    cfg.gridDim  = dim3(GRID, 1, 1);
    cfg.blockDim = dim3(THREADS, 1, 1);
    cfg.dynamicSmemBytes = SMEM_BYTES;
    cfg.stream = 0;
    cfg.attrs = attrs;
    cfg.numAttrs = 1;
    cudaLaunchKernelEx(&cfg, relnet_kernel, emb, weight, bias, out);
}

// round 16
// speedup vs baseline: 1.0935x; 1.0935x over previous
#include <cuda_runtime.h>

// Problem constants (fixed by setup_inputs): B=8, N=20, K=5, Q=15, D=1024
#define BB     8
#define NN     20
#define KSUP   5
#define QQ     15
#define DD     1024
#define ROWS   (KSUP + QQ)        // 20 rows per (b,n)
#define NQ     (NN * QQ)          // 300 queries per batch
#define WARPS  16
#define THREADS 512
#define BPB    19                 // blocks per batch (19*16=304 >= 300 queries)
#define GRID   (BB * BPB)         // 152 blocks == GB300 SM count, single wave

// Scratch (device globals — no allocation allowed)
__device__ float g_proto[BB * NN * DD];   // 640 KB, L2-resident
__device__ float g_termp[BB * NN];

// ---------------------------------------------------------------------------
// K1: proto[b,n,:] = mean_j support, term_p[b,n] = proto . w0  (computed ONCE,
// off relnet's critical path). Triggers PDL completion for relnet's overlap.
// ---------------------------------------------------------------------------
__global__ __launch_bounds__(256) void proto_kernel(
    const float* __restrict__ emb, const float* __restrict__ weight)
{
    int bn = blockIdx.x;             // b*20 + n
    int t  = threadIdx.x;            // float4 index 0..255
    const float4* base = reinterpret_cast<const float4*>(emb) + (size_t)bn * ROWS * 256;

    float4 s = base[t];
#pragma unroll
    for (int j = 1; j < KSUP; j++) {
        float4 v = base[j * 256 + t];
        s.x += v.x; s.y += v.y; s.z += v.z; s.w += v.w;
    }
    s.x *= 0.2f; s.y *= 0.2f; s.z *= 0.2f; s.w *= 0.2f;
    reinterpret_cast<float4*>(g_proto)[(size_t)bn * 256 + t] = s;

    float4 w0 = reinterpret_cast<const float4*>(weight)[t];
    float tp = s.x * w0.x + s.y * w0.y + s.z * w0.z + s.w * w0.w;
#pragma unroll
    for (int off = 16; off; off >>= 1) tp += __shfl_xor_sync(0xFFFFFFFFu, tp, off);

    __shared__ float red[8];
    if ((t & 31) == 0) red[t >> 5] = tp;
    __syncthreads();
    if (t == 0) {
        float r = 0.f;
#pragma unroll
        for (int w = 0; w < 8; w++) r += red[w];
        g_termp[bn] = r;
    }
    cudaTriggerProgrammaticLaunchCompletion();
}

// ---------------------------------------------------------------------------
// Main: 152 blocks (= SM count) x 512 threads, one batch per block, single
// wave. R11's exact hot loop + fill (proto/w2/termp from globals), with R14's
// PDL prolog: query/weight LDGs and all register-only math issued BEFORE
// cudaGridDependencySynchronize(); only the g_proto/g_termp fill waits.
// ---------------------------------------------------------------------------
__global__ __launch_bounds__(THREADS, 1) void relnet_kernel(
    const float* __restrict__ emb,
    const float* __restrict__ weight,
    const float* __restrict__ bias,
    float* __restrict__ out)
{
    extern __shared__ float smem[];
    float4* sP4 = reinterpret_cast<float4*>(smem);               // 20*256 f4 = 81920 B
    float4* sW2 = reinterpret_cast<float4*>(smem + NN * DD);     // 256 f4    =  4096 B
    float*  sTp = smem + NN * DD + 1024;                         // 20 floats

    const int tid  = threadIdx.x;
    const int lane = tid & 31;
    const int warp = tid >> 5;

    const int b      = blockIdx.x / BPB;          // batch
    const int blkInB = blockIdx.x - b * BPB;      // 0..18
    const int q      = blkInB * WARPS + warp;     // 0..303
    const bool active = (q < NQ);
    const int qc     = active ? q : (NQ - 1);     // clamped for safe addressing

    const float4* emb4 = reinterpret_cast<const float4*>(emb);
    const float4* w14  = reinterpret_cast<const float4*>(weight) + 1 * 256;
    const float4* w24  = reinterpret_cast<const float4*>(weight) + 2 * 256;
    const float4* w34  = reinterpret_cast<const float4*>(weight) + 3 * 256;
    const float4* gP4  = reinterpret_cast<const float4*>(g_proto);
    const float bi = bias[0];

    // ---- PDL prolog: LDGs that do NOT depend on proto output ----
    const int qrow = (b * NN + qc / QQ) * ROWS + KSUP + qc % QQ;
    const float4* r = emb4 + (size_t)qrow * 256;

    float4 av[8], w3v[8], w1v[8];
#pragma unroll
    for (int i = 0; i < 8; i++) {
        const int idx = i * 32 + lane;
        av[i]  = r[idx];
        w3v[i] = w34[idx];
        w1v[i] = w14[idx];
    }
    if (tid < 256) sW2[tid] = w24[tid];

    // register-only derivation (still before the dependency sync)
    float qv[32], cv[32];
    float tq = 0.f;
#pragma unroll
    for (int i = 0; i < 8; i++) {
        const float4 a  = av[i];
        const float4 w3 = w3v[i];
        const float4 w1 = w1v[i];
        qv[4*i+0] = a.x; qv[4*i+1] = a.y; qv[4*i+2] = a.z; qv[4*i+3] = a.w;
        cv[4*i+0] = a.x * w3.x; cv[4*i+1] = a.y * w3.y;
        cv[4*i+2] = a.z * w3.z; cv[4*i+3] = a.w * w3.w;
        tq = fmaf(a.x, w1.x, tq); tq = fmaf(a.y, w1.y, tq);
        tq = fmaf(a.z, w1.z, tq); tq = fmaf(a.w, w1.w, tq);
    }
#pragma unroll
    for (int off = 16; off; off >>= 1) tq += __shfl_xor_sync(0xFFFFFFFFu, tq, off);

    // ---- wait for proto kernel, then fill smem (proto tile + termp) ----
    cudaGridDependencySynchronize();
#pragma unroll
    for (int k = 0; k < 10; k++) {
        const int idx = k * THREADS + tid;
        sP4[idx] = gP4[(size_t)b * NN * 256 + idx];
    }
    if (tid < NN) sTp[tid] = g_termp[b * NN + tid];
    __syncthreads();

    if (!active) return;

    float* o = out + ((size_t)b * NQ + q) * NN;

    // ---- R11 hot loop: 5 n-blocks of 4, double-buffered LDS prefetch ----
#pragma unroll 1
    for (int nb = 0; nb < 5; nb++) {
        const float4* pb = sP4 + nb * 4 * 256 + lane;

        float acc[4] = {0.f, 0.f, 0.f, 0.f};
        float4 pc[4], w2c;
        w2c = sW2[lane];
#pragma unroll
        for (int n = 0; n < 4; n++) pc[n] = pb[n * 256];

#pragma unroll
        for (int i = 0; i < 8; i++) {
            float4 pn[4], w2n;
            if (i < 7) {                       // prefetch batch i+1
                w2n = sW2[(i + 1) * 32 + lane];
#pragma unroll
                for (int n = 0; n < 4; n++) pn[n] = pb[n * 256 + (i + 1) * 32];
            }
#pragma unroll
            for (int n = 0; n < 4; n++) {
                const float4 p = pc[n];
                acc[n] = fmaf(fabsf(p.x - qv[4*i+0]), w2c.x, acc[n]);
                acc[n] = fmaf(p.x, cv[4*i+0], acc[n]);
                acc[n] = fmaf(fabsf(p.y - qv[4*i+1]), w2c.y, acc[n]);
                acc[n] = fmaf(p.y, cv[4*i+1], acc[n]);
                acc[n] = fmaf(fabsf(p.z - qv[4*i+2]), w2c.z, acc[n]);
                acc[n] = fmaf(p.z, cv[4*i+2], acc[n]);
                acc[n] = fmaf(fabsf(p.w - qv[4*i+3]), w2c.w, acc[n]);
                acc[n] = fmaf(p.w, cv[4*i+3], acc[n]);
            }
            if (i < 7) {
#pragma unroll
                for (int n = 0; n < 4; n++) pc[n] = pn[n];
                w2c = w2n;
            }
        }

        // deferred reductions: 4 independent butterflies per n-block
#pragma unroll
        for (int n = 0; n < 4; n++) {
            float s = acc[n];
#pragma unroll
            for (int off = 16; off; off >>= 1)
                s += __shfl_xor_sync(0xFFFFFFFFu, s, off);
            acc[n] = s;
        }
        if (lane == 0) {
#pragma unroll
            for (int n = 0; n < 4; n++) {
                const int nn = nb * 4 + n;
                o[nn] = acc[n] + sTp[nn] + tq + bi;
            }
        }
    }
}

// ---------------------------------------------------------------------------
// Launch: proto (with termp) then relnet with PDL so relnet's prolog
// overlaps proto's tail.
// ---------------------------------------------------------------------------
static const int SMEM_BYTES = (NN * DD + 1024 + 32) * (int)sizeof(float); // 86,144 B

extern "C" void kernel_launch(void* const* d_in, const int* in_sizes, int n_in,
                              void* d_out, int out_size)
{
    const float* emb    = (const float*)d_in[0];
    const float* weight = (const float*)d_in[1];
    const float* bias   = (const float*)d_in[2];
    float* out          = (float*)d_out;

    cudaFuncSetAttribute(relnet_kernel,
                         cudaFuncAttributeMaxDynamicSharedMemorySize, SMEM_BYTES);

    proto_kernel<<<BB * NN, 256>>>(emb, weight);

    cudaLaunchAttribute attrs[1];
    attrs[0].id = cudaLaunchAttributeProgrammaticStreamSerialization;
    attrs[0].val.programmaticStreamSerializationAllowed = 1;

    cudaLaunchConfig_t cfg = {};
    cfg.gridDim  = dim3(GRID, 1, 1);
    cfg.blockDim = dim3(THREADS, 1, 1);
    cfg.dynamicSmemBytes = SMEM_BYTES;
    cfg.stream = 0;
    cfg.attrs = attrs;
    cfg.numAttrs = 1;
    cudaLaunchKernelEx(&cfg, relnet_kernel, emb, weight, bias, out);
}

// round 17
// speedup vs baseline: 1.1101x; 1.0152x over previous
#include <cuda_runtime.h>

// Problem constants (fixed by setup_inputs): B=8, N=20, K=5, Q=15, D=1024
#define BB     8
#define NN     20
#define KSUP   5
#define QQ     15
#define DD     1024
#define ROWS   (KSUP + QQ)        // 20 rows per (b,n)
#define NQ     (NN * QQ)          // 300 queries per batch
#define WARPS  16
#define THREADS 512
#define BPB    19                 // blocks per batch (19*16=304 >= 300 queries)
#define GRID   (BB * BPB)         // 152 blocks == GB300 SM count, single wave

// Scratch (device globals — no allocation allowed)
__device__ float g_proto[BB * NN * DD];   // 640 KB, L2-resident
__device__ float g_termp2[BB * NN * 2];   // per-D-half partial termp

// ---------------------------------------------------------------------------
// K1 (slim): block = (bn, D-half), 128 threads. Computes the proto mean for
// its half AND the per-half partial termp dot (4-warp block reduction, fully
// parallel across 320 blocks). Triggers PDL completion for relnet overlap.
// ---------------------------------------------------------------------------
__global__ __launch_bounds__(128) void proto_kernel(
    const float* __restrict__ emb, const float* __restrict__ weight)
{
    const int bn   = blockIdx.x >> 1;
    const int half = blockIdx.x & 1;
    const int t    = threadIdx.x;             // f4 index within half
    const float4* base = reinterpret_cast<const float4*>(emb)
                       + (size_t)bn * ROWS * 256 + half * 128 + t;
    float4 s = base[0];
#pragma unroll
    for (int j = 1; j < KSUP; j++) {
        const float4 v = base[j * 256];
        s.x += v.x; s.y += v.y; s.z += v.z; s.w += v.w;
    }
    s.x *= 0.2f; s.y *= 0.2f; s.z *= 0.2f; s.w *= 0.2f;
    reinterpret_cast<float4*>(g_proto)[(size_t)bn * 256 + half * 128 + t] = s;

    // per-half termp partial: dot(proto_half, w0_half)
    const float4 w0 = reinterpret_cast<const float4*>(weight)[half * 128 + t];
    float tp = s.x * w0.x + s.y * w0.y + s.z * w0.z + s.w * w0.w;
#pragma unroll
    for (int off = 16; off; off >>= 1) tp += __shfl_xor_sync(0xFFFFFFFFu, tp, off);

    __shared__ float red[4];
    if ((t & 31) == 0) red[t >> 5] = tp;
    __syncthreads();
    if (t == 0)
        g_termp2[bn * 2 + half] = red[0] + red[1] + red[2] + red[3];

    cudaTriggerProgrammaticLaunchCompletion();
}

// ---------------------------------------------------------------------------
// Main: 152 blocks (= SM count) x 512 threads, one batch per block, single
// wave. R16's relnet verbatim except sTp = sum of the two termp halves.
// PDL prolog: query/weight LDGs + register math before the dependency sync.
// ---------------------------------------------------------------------------
__global__ __launch_bounds__(THREADS, 1) void relnet_kernel(
    const float* __restrict__ emb,
    const float* __restrict__ weight,
    const float* __restrict__ bias,
    float* __restrict__ out)
{
    extern __shared__ float smem[];
    float4* sP4 = reinterpret_cast<float4*>(smem);               // 20*256 f4 = 81920 B
    float4* sW2 = reinterpret_cast<float4*>(smem + NN * DD);     // 256 f4    =  4096 B
    float*  sTp = smem + NN * DD + 1024;                         // 20 floats

    const int tid  = threadIdx.x;
    const int lane = tid & 31;
    const int warp = tid >> 5;

    const int b      = blockIdx.x / BPB;          // batch
    const int blkInB = blockIdx.x - b * BPB;      // 0..18
    const int q      = blkInB * WARPS + warp;     // 0..303
    const bool active = (q < NQ);
    const int qc     = active ? q : (NQ - 1);     // clamped for safe addressing

    const float4* emb4 = reinterpret_cast<const float4*>(emb);
    const float4* w14  = reinterpret_cast<const float4*>(weight) + 1 * 256;
    const float4* w24  = reinterpret_cast<const float4*>(weight) + 2 * 256;
    const float4* w34  = reinterpret_cast<const float4*>(weight) + 3 * 256;
    const float4* gP4  = reinterpret_cast<const float4*>(g_proto);
    const float bi = bias[0];

    // ---- PDL prolog: LDGs that do NOT depend on proto output ----
    const int qrow = (b * NN + qc / QQ) * ROWS + KSUP + qc % QQ;
    const float4* r = emb4 + (size_t)qrow * 256;

    float4 av[8], w3v[8], w1v[8];
#pragma unroll
    for (int i = 0; i < 8; i++) {
        const int idx = i * 32 + lane;
        av[i]  = r[idx];
        w3v[i] = w34[idx];
        w1v[i] = w14[idx];
    }
    if (tid < 256) sW2[tid] = w24[tid];

    // register-only derivation (still before the dependency sync)
    float qv[32], cv[32];
    float tq = 0.f;
#pragma unroll
    for (int i = 0; i < 8; i++) {
        const float4 a  = av[i];
        const float4 w3 = w3v[i];
        const float4 w1 = w1v[i];
        qv[4*i+0] = a.x; qv[4*i+1] = a.y; qv[4*i+2] = a.z; qv[4*i+3] = a.w;
        cv[4*i+0] = a.x * w3.x; cv[4*i+1] = a.y * w3.y;
        cv[4*i+2] = a.z * w3.z; cv[4*i+3] = a.w * w3.w;
        tq = fmaf(a.x, w1.x, tq); tq = fmaf(a.y, w1.y, tq);
        tq = fmaf(a.z, w1.z, tq); tq = fmaf(a.w, w1.w, tq);
    }
#pragma unroll
    for (int off = 16; off; off >>= 1) tq += __shfl_xor_sync(0xFFFFFFFFu, tq, off);

    // ---- wait for proto kernel, then fill smem (proto tile + termp) ----
    cudaGridDependencySynchronize();
#pragma unroll
    for (int k = 0; k < 10; k++) {
        const int idx = k * THREADS + tid;
        sP4[idx] = gP4[(size_t)b * NN * 256 + idx];
    }
    if (tid < NN)
        sTp[tid] = g_termp2[(b * NN + tid) * 2] + g_termp2[(b * NN + tid) * 2 + 1];
    __syncthreads();

    if (!active) return;

    float* o = out + ((size_t)b * NQ + q) * NN;

    // ---- R11/R16 hot loop: 5 n-blocks of 4, double-buffered LDS prefetch ----
#pragma unroll 1
    for (int nb = 0; nb < 5; nb++) {
        const float4* pb = sP4 + nb * 4 * 256 + lane;

        float acc[4] = {0.f, 0.f, 0.f, 0.f};
        float4 pc[4], w2c;
        w2c = sW2[lane];
#pragma unroll
        for (int n = 0; n < 4; n++) pc[n] = pb[n * 256];

#pragma unroll
        for (int i = 0; i < 8; i++) {
            float4 pn[4], w2n;
            if (i < 7) {                       // prefetch batch i+1
                w2n = sW2[(i + 1) * 32 + lane];
#pragma unroll
                for (int n = 0; n < 4; n++) pn[n] = pb[n * 256 + (i + 1) * 32];
            }
#pragma unroll
            for (int n = 0; n < 4; n++) {
                const float4 p = pc[n];
                acc[n] = fmaf(fabsf(p.x - qv[4*i+0]), w2c.x, acc[n]);
                acc[n] = fmaf(p.x, cv[4*i+0], acc[n]);
                acc[n] = fmaf(fabsf(p.y - qv[4*i+1]), w2c.y, acc[n]);
                acc[n] = fmaf(p.y, cv[4*i+1], acc[n]);
                acc[n] = fmaf(fabsf(p.z - qv[4*i+2]), w2c.z, acc[n]);
                acc[n] = fmaf(p.z, cv[4*i+2], acc[n]);
                acc[n] = fmaf(fabsf(p.w - qv[4*i+3]), w2c.w, acc[n]);
                acc[n] = fmaf(p.w, cv[4*i+3], acc[n]);
            }
            if (i < 7) {
#pragma unroll
                for (int n = 0; n < 4; n++) pc[n] = pn[n];
                w2c = w2n;
            }
        }

        // deferred reductions: 4 independent butterflies per n-block
#pragma unroll
        for (int n = 0; n < 4; n++) {
            float s = acc[n];
#pragma unroll
            for (int off = 16; off; off >>= 1)
                s += __shfl_xor_sync(0xFFFFFFFFu, s, off);
            acc[n] = s;
        }
        if (lane == 0) {
#pragma unroll
            for (int n = 0; n < 4; n++) {
                const int nn = nb * 4 + n;
                o[nn] = acc[n] + sTp[nn] + tq + bi;
            }
        }
    }
}

// ---------------------------------------------------------------------------
// Launch: slim proto (with per-half termp) then relnet with PDL.
// ---------------------------------------------------------------------------
static const int SMEM_BYTES = (NN * DD + 1024 + 32) * (int)sizeof(float); // 86,144 B

extern "C" void kernel_launch(void* const* d_in, const int* in_sizes, int n_in,
                              void* d_out, int out_size)
{
    const float* emb    = (const float*)d_in[0];
    const float* weight = (const float*)d_in[1];
    const float* bias   = (const float*)d_in[2];
    float* out          = (float*)d_out;

    cudaFuncSetAttribute(relnet_kernel,
                         cudaFuncAttributeMaxDynamicSharedMemorySize, SMEM_BYTES);

    proto_kernel<<<BB * NN * 2, 128>>>(emb, weight);

    cudaLaunchAttribute attrs[1];
    attrs[0].id = cudaLaunchAttributeProgrammaticStreamSerialization;
    attrs[0].val.programmaticStreamSerializationAllowed = 1;

    cudaLaunchConfig_t cfg = {};
    cfg.gridDim  = dim3(GRID, 1, 1);
    cfg.blockDim = dim3(THREADS, 1, 1);
    cfg.dynamicSmemBytes = SMEM_BYTES;
    cfg.stream = 0;
    cfg.attrs = attrs;
    cfg.numAttrs = 1;
    cudaLaunchKernelEx(&cfg, relnet_kernel, emb, weight, bias, out);
}